// round 8
// baseline (speedup 1.0000x reference)
#include <cuda_runtime.h>
#include <cstdint>

#define TSTEPS 2048
#define BATCH  128
#define HID    256
#define INDIM  82
#define CLU    8
#define BPC    8
#define NTHR   512

#define HROW    272              // padded floats per batch row: 4 chunks of 68
#define HBUFLEN (BPC*HROW)       // 2176 floats per phase

// ---- shared memory layout (bytes) ----
#define OFF_WIH   0                       // [col][ro] ro = ul*4+g (unit-major)
#define SZ_WIH    (INDIM*128*4)           // 41984
#define OFF_BIAS  (OFF_WIH + SZ_WIH)      // 41984
#define SZ_BIAS   (512)
#define OFF_HBUF  (OFF_BIAS + SZ_BIAS)    // 42496 (16B aligned)
#define SZ_HBUF   (2*HBUFLEN*4)           // 17408
#define OFF_MBAR  (OFF_HBUF + SZ_HBUF)    // 59904
#define SMEM_TOTAL (OFF_MBAR + 16)

#define EXCH_BYTES (CLU*BPC*32*4)         // 8192 B arriving per phase per CTA

typedef unsigned long long ull;

__device__ __forceinline__ ull fma2(ull a, ull b, ull c){
  ull d; asm("fma.rn.f32x2 %0, %1, %2, %3;" : "=l"(d) : "l"(a),"l"(b),"l"(c)); return d;
}
__device__ __forceinline__ float lo32(ull v){ return __uint_as_float((unsigned)(v & 0xffffffffull)); }
__device__ __forceinline__ float hi32(ull v){ return __uint_as_float((unsigned)(v >> 32)); }
__device__ __forceinline__ float sigf(float x){ return __fdividef(1.f, 1.f + __expf(-x)); }
__device__ __forceinline__ float tanhf_(float x){ return __fdividef(2.f, 1.f + __expf(-2.f*x)) - 1.f; }
__device__ __forceinline__ uint32_t s2u(const void* p){
  uint32_t a;
  asm("{.reg .u64 t; cvta.to.shared.u64 t, %1; cvt.u32.u64 %0, t;}" : "=r"(a) : "l"(p));
  return a;
}
__device__ __forceinline__ void mbar_init(uint32_t m, int cnt){
  asm volatile("mbarrier.init.shared.b64 [%0], %1;" :: "r"(m), "r"(cnt) : "memory");
}
__device__ __forceinline__ void mbar_arm(uint32_t m, int bytes){
  asm volatile("mbarrier.arrive.expect_tx.shared.b64 _, [%0], %1;" :: "r"(m), "r"(bytes) : "memory");
}
__device__ __forceinline__ void mbar_wait(uint32_t m, uint32_t parity){
  asm volatile(
    "{\n\t.reg .pred P;\n\t"
    "WLP%=:\n\t"
    "mbarrier.try_wait.parity.acquire.cluster.shared::cta.b64 P, [%0], %1, 0x989680;\n\t"
    "@!P bra WLP%=;\n\t}"
    :: "r"(m), "r"(parity) : "memory");
}
__device__ __forceinline__ void st_async_f32(uint32_t raddr, float v, uint32_t rmbar){
  asm volatile("st.async.shared::cluster.mbarrier::complete_tx::bytes.b32 [%0], %1, [%2];"
               :: "r"(raddr), "r"(__float_as_uint(v)), "r"(rmbar) : "memory");
}
__device__ __forceinline__ uint32_t mapa_u32(uint32_t la, int rank){
  uint32_t ra;
  asm("mapa.shared::cluster.u32 %0, %1, %2;" : "=r"(ra) : "r"(la), "r"(rank));
  return ra;
}

extern __shared__ char smem[];

__global__ void __cluster_dims__(CLU,1,1) __launch_bounds__(NTHR,1)
lstm_scan_kernel(const int* __restrict__ X, const float* __restrict__ H0,
                 const int* __restrict__ A, const float* __restrict__ R,
                 const float* __restrict__ Dn,
                 const float* __restrict__ Wih, const float* __restrict__ Whh,
                 const float* __restrict__ bih, const float* __restrict__ bhh,
                 float* __restrict__ out)
{
  const int tid = threadIdx.x;
  const int uc  = blockIdx.x & (CLU-1);   // cluster rank: which 32 hidden units
  const int bg  = blockIdx.x / CLU;       // batch group of 8
  const int gb0 = bg * BPC;

  float* WihT  = (float*)(smem + OFF_WIH);
  float* biasS = (float*)(smem + OFF_BIAS);
  float* hbuf  = (float*)(smem + OFF_HBUF);

  const uint32_t sb = s2u(smem);

  // ---- lane identity: lane = u'(b4) | gq(b3:2) | kc(b1:0) ----
  const int w    = tid >> 5;
  const int lane = tid & 31;
  const int up   = lane >> 4;          // which of the warp's 2 units
  const int gq   = (lane >> 2) & 3;    // gate (i,f,g,o)
  const int kc   = lane & 3;           // k-chunk of 64
  const int ul   = w*2 + up;           // local unit 0..31
  const int ug   = uc*32 + ul;         // global unit 0..255
  const int ro   = ul*4 + gq;          // unit-major row index for WihT/bias
  const int gr   = gq*HID + ug;        // global gate-row in W

  // ---- weight-stationary: this lane's 64 W_hh floats in registers ----
  ull wv[32];
  {
    const ulonglong2* Wg = (const ulonglong2*)(Whh + (size_t)gr*HID + kc*64);
    #pragma unroll
    for (int j = 0; j < 16; ++j){
      ulonglong2 u = Wg[j];
      wv[2*j] = u.x; wv[2*j+1] = u.y;
    }
  }

  // ---- one-time smem staging ----
  for (int i = tid; i < INDIM*128; i += NTHR){
    int c0 = i >> 7, r = i & 127;
    int uu = r >> 2, g = r & 3;
    WihT[c0*128 + r] = Wih[(g*HID + uc*32 + uu)*INDIM + c0];
  }
  for (int i = tid; i < 128; i += NTHR){
    int uu = i >> 2, g = i & 3;
    int grr = g*HID + uc*32 + uu;
    biasS[i] = bih[grr] + bhh[grr];
  }
  for (int i = tid; i < BPC*HID; i += NTHR){
    int b = i >> 8, k = i & 255;
    hbuf[b*HROW + (k >> 6)*68 + (k & 63)] = H0[(gb0 + b)*(2*HID) + k];
  }

  if (tid == 0){
    mbar_init(sb + OFF_MBAR,     1);
    mbar_init(sb + OFF_MBAR + 8, 1);
    mbar_arm (sb + OFF_MBAR,     EXCH_BYTES);
    mbar_arm (sb + OFF_MBAR + 8, EXCH_BYTES);
  }
  __syncthreads();
  asm volatile("barrier.cluster.arrive.aligned;" ::: "memory");
  asm volatile("barrier.cluster.wait.aligned;"   ::: "memory");

  // per-lane constants from smem (after staging)
  const float w80 = WihT[80*128 + ro];
  const float w81 = WihT[81*128 + ro];
  const float bs  = biasS[ro];

  // cell state for this unit, all 8 batches (redundant across the 16 lanes of a unit)
  float cst[8], hl[8];
  #pragma unroll
  for (int b = 0; b < 8; ++b){
    cst[b] = H0[(gb0 + b)*(2*HID) + HID + ug];
    hl[b] = 0.f;
  }

  // remote CTA smem bases
  uint32_t ra[CLU];
  #pragma unroll
  for (int p = 0; p < CLU; ++p) ra[p] = mapa_u32(sb, p);

  // exchange: lanes j = gq*4+kc < 8 send to CTA p=j (covers both u' groups)
  const int j16 = gq*4 + kc;
  const bool sender = (j16 < 8);
  const bool writer = (j16 == 0);
  const uint32_t raj = sender ? ra[j16] : 0;
  const unsigned hoff_u = 4u*(unsigned)((ug >> 6)*68 + (ug & 63));  // within b-row

  // input fetch identity: lane sel/bb
  const int sel = lane >> 3, bb = lane & 7;
  const unsigned* ipb;
  {
    const unsigned* p = (sel == 0) ? (const unsigned*)X :
                        (sel == 1) ? (const unsigned*)A :
                        (sel == 2) ? (const unsigned*)R : (const unsigned*)Dn;
    ipb = p + (size_t)(gb0 + bb)*TSTEPS;
  }

  uint32_t ph0 = 0, ph1 = 0;

  #pragma unroll 1
  for (int t = 0; t < TSTEPS; ++t){
    const int cb = t & 1;
    const int nb = cb ^ 1;

    // issue input load before the wait (independent of h)
    unsigned inw = ipb[t];

    if (t > 0){
      uint32_t m = sb + OFF_MBAR + cb*8;
      uint32_t par = cb ? ph1 : ph0;
      mbar_wait(m, par);
      if (cb) ph1 ^= 1; else ph0 ^= 1;
      if (tid == 0) mbar_arm(m, EXCH_BYTES);
    }

    const float* hB = hbuf + cb*HBUFLEN;
    const unsigned nboff = (unsigned)(OFF_HBUF) + (unsigned)(nb*HBUFLEN*4);
    const unsigned moff  = (unsigned)(OFF_MBAR + nb*8);

    #pragma unroll
    for (int b = 0; b < 8; ++b){
      // ---- GEMM partial: this lane's gate row x h[b][kc*64..+64) ----
      const ulonglong2* hp = (const ulonglong2*)(hB + b*HROW + kc*68);
      ull a0 = 0, a1 = 0;
      #pragma unroll
      for (int j = 0; j < 8; ++j){
        ulonglong2 u = hp[j];
        a0 = fma2(wv[2*j],     u.x, a0);
        a0 = fma2(wv[2*j+1],   u.y, a0);
      }
      #pragma unroll
      for (int j = 8; j < 16; ++j){
        ulonglong2 u = hp[j];
        a1 = fma2(wv[2*j],     u.x, a1);
        a1 = fma2(wv[2*j+1],   u.y, a1);
      }
      ull asum = fma2(a0, 0x3f8000003f800000ull /*1.0,1.0*/, a1); // a0+a1 packed
      float s = lo32(asum) + hi32(asum);

      // reduce over kc (lane bits 0-1)
      s += __shfl_xor_sync(0xffffffffu, s, 1);
      s += __shfl_xor_sync(0xffffffffu, s, 2);

      // x_proj for this lane's gate
      int   xi = __shfl_sync(0xffffffffu, (int)inw, b);
      int   ai = __shfl_sync(0xffffffffu, (int)inw, 8 + b);
      float rv = __uint_as_float(__shfl_sync(0xffffffffu, inw, 16 + b));
      float dv = __uint_as_float(__shfl_sync(0xffffffffu, inw, 24 + b));
      float gate = s + WihT[xi*128 + ro] + WihT[(64 + ai)*128 + ro]
                 + w80*rv + w81*dv + bs;

      // activation of own gate (tanh for g-gate, sigmoid otherwise)
      float act = (gq == 2) ? tanhf_(gate) : sigf(gate);

      // gather i,f,g,o across gate lanes (bits 2-3)
      float axa = __shfl_xor_sync(0xffffffffu, act, 4);
      float e0 = (gq & 1) ? axa : act;   // act(gq & ~1)
      float e1 = (gq & 1) ? act : axa;   // act(gq | 1)
      float f0 = __shfl_xor_sync(0xffffffffu, e0, 8);
      float f1 = __shfl_xor_sync(0xffffffffu, e1, 8);
      float vI = (gq < 2) ? e0 : f0;
      float vF = (gq < 2) ? e1 : f1;
      float vG = (gq < 2) ? f0 : e0;
      float vO = (gq < 2) ? f1 : e1;

      float cc = vF*cst[b] + vI*vG;
      cst[b] = cc;
      float hv = vO * tanhf_(cc);
      hl[b] = hv;

      // features[b][t][u]
      if (writer)
        out[((size_t)(gb0 + b)*TSTEPS + t)*HID + ug] = hv;

      // send h for step t+1 to all CTAs (8 sender lanes x 2 units)
      if (t < TSTEPS-1 && sender){
        unsigned ho = nboff + (unsigned)(b*HROW*4) + hoff_u;
        st_async_f32(raj + ho, hv, raj + moff);
      }
    }
  }

  // final_hidden = [hT | cT]
  if (writer){
    size_t fo = (size_t)BATCH*TSTEPS*HID;
    #pragma unroll
    for (int b = 0; b < 8; ++b){
      out[fo + (size_t)(gb0 + b)*(2*HID) + ug]       = hl[b];
      out[fo + (size_t)(gb0 + b)*(2*HID) + HID + ug] = cst[b];
    }
  }

  asm volatile("barrier.cluster.arrive.aligned;" ::: "memory");
  asm volatile("barrier.cluster.wait.aligned;"   ::: "memory");
}

extern "C" void kernel_launch(void* const* d_in, const int* in_sizes, int n_in,
                              void* d_out, int out_size)
{
  const int*   X   = (const int*)  d_in[0];
  const float* H0  = (const float*)d_in[1];
  const int*   A   = (const int*)  d_in[2];
  const float* R   = (const float*)d_in[3];
  const float* Dn  = (const float*)d_in[4];
  const float* Wih = (const float*)d_in[5];
  const float* Whh = (const float*)d_in[6];
  const float* bih = (const float*)d_in[7];
  const float* bhh = (const float*)d_in[8];
  float* out = (float*)d_out;

  cudaFuncSetAttribute(lstm_scan_kernel,
                       cudaFuncAttributeMaxDynamicSharedMemorySize, SMEM_TOTAL);
  lstm_scan_kernel<<<BATCH, NTHR, SMEM_TOTAL>>>(X, H0, A, R, Dn, Wih, Whh, bih, bhh, out);
}

// round 9
// speedup vs baseline: 1.0004x; 1.0004x over previous
#include <cuda_runtime.h>
#include <cstdint>

#define TSTEPS 2048
#define BATCH  128
#define HID    256
#define INDIM  82
#define CLU    8
#define BPC    8
#define NTHR   512

#define HROW    272              // padded floats per batch row: 4 chunks of 68
#define HBUFLEN (BPC*HROW)       // 2176 floats per phase

// ---- shared memory layout (bytes) ----
#define OFF_WIH   0                       // [col][ro] ro = ul*4+g (unit-major)
#define SZ_WIH    (INDIM*128*4)           // 41984
#define OFF_BIAS  (OFF_WIH + SZ_WIH)      // 41984
#define SZ_BIAS   (512)
#define OFF_HBUF  (OFF_BIAS + SZ_BIAS)    // 42496 (16B aligned)
#define SZ_HBUF   (2*HBUFLEN*4)           // 17408
#define OFF_MBAR  (OFF_HBUF + SZ_HBUF)    // 59904
#define SMEM_TOTAL (OFF_MBAR + 16)

#define EXCH_BYTES (CLU*BPC*32*4)         // 8192 B arriving per phase per CTA

typedef unsigned long long ull;

__device__ __forceinline__ ull fma2(ull a, ull b, ull c){
  ull d; asm("fma.rn.f32x2 %0, %1, %2, %3;" : "=l"(d) : "l"(a),"l"(b),"l"(c)); return d;
}
__device__ __forceinline__ float lo32(ull v){ return __uint_as_float((unsigned)(v & 0xffffffffull)); }
__device__ __forceinline__ float hi32(ull v){ return __uint_as_float((unsigned)(v >> 32)); }
__device__ __forceinline__ float sigf(float x){ return __fdividef(1.f, 1.f + __expf(-x)); }
__device__ __forceinline__ float tanhf_(float x){ return __fdividef(2.f, 1.f + __expf(-2.f*x)) - 1.f; }
__device__ __forceinline__ uint32_t s2u(const void* p){
  uint32_t a;
  asm("{.reg .u64 t; cvta.to.shared.u64 t, %1; cvt.u32.u64 %0, t;}" : "=r"(a) : "l"(p));
  return a;
}
__device__ __forceinline__ void mbar_init(uint32_t m, int cnt){
  asm volatile("mbarrier.init.shared.b64 [%0], %1;" :: "r"(m), "r"(cnt) : "memory");
}
__device__ __forceinline__ void mbar_arm(uint32_t m, int bytes){
  asm volatile("mbarrier.arrive.expect_tx.shared.b64 _, [%0], %1;" :: "r"(m), "r"(bytes) : "memory");
}
__device__ __forceinline__ void mbar_wait(uint32_t m, uint32_t parity){
  asm volatile(
    "{\n\t.reg .pred P;\n\t"
    "WLP%=:\n\t"
    "mbarrier.try_wait.parity.acquire.cluster.shared::cta.b64 P, [%0], %1, 0x989680;\n\t"
    "@!P bra WLP%=;\n\t}"
    :: "r"(m), "r"(parity) : "memory");
}
__device__ __forceinline__ void st_async_f32(uint32_t raddr, float v, uint32_t rmbar){
  asm volatile("st.async.shared::cluster.mbarrier::complete_tx::bytes.b32 [%0], %1, [%2];"
               :: "r"(raddr), "r"(__float_as_uint(v)), "r"(rmbar) : "memory");
}
__device__ __forceinline__ uint32_t mapa_u32(uint32_t la, int rank){
  uint32_t ra;
  asm("mapa.shared::cluster.u32 %0, %1, %2;" : "=r"(ra) : "r"(la), "r"(rank));
  return ra;
}

extern __shared__ char smem[];

__global__ void __cluster_dims__(CLU,1,1) __launch_bounds__(NTHR,1)
lstm_scan_kernel(const int* __restrict__ X, const float* __restrict__ H0,
                 const int* __restrict__ A, const float* __restrict__ R,
                 const float* __restrict__ Dn,
                 const float* __restrict__ Wih, const float* __restrict__ Whh,
                 const float* __restrict__ bih, const float* __restrict__ bhh,
                 float* __restrict__ out)
{
  const int tid = threadIdx.x;
  const int uc  = blockIdx.x & (CLU-1);   // cluster rank: which 32 hidden units
  const int bg  = blockIdx.x / CLU;       // batch group of 8
  const int gb0 = bg * BPC;

  float* WihT  = (float*)(smem + OFF_WIH);
  float* biasS = (float*)(smem + OFF_BIAS);
  float* hbuf  = (float*)(smem + OFF_HBUF);

  const uint32_t sb = s2u(smem);

  // ---- lane identity: lane = u'(b4) | gq(b3:2) | kc(b1:0) ----
  const int w    = tid >> 5;
  const int lane = tid & 31;
  const int up   = lane >> 4;          // which of the warp's 2 units
  const int gq   = (lane >> 2) & 3;    // gate (i,f,g,o)
  const int kc   = lane & 3;           // k-chunk of 64
  const int ul   = w*2 + up;           // local unit 0..31
  const int ug   = uc*32 + ul;         // global unit 0..255
  const int ro   = ul*4 + gq;          // unit-major row index for WihT/bias
  const int gr   = gq*HID + ug;        // global gate-row in W

  // ---- weight-stationary: this lane's 64 W_hh floats in registers ----
  ull wv[32];
  {
    const ulonglong2* Wg = (const ulonglong2*)(Whh + (size_t)gr*HID + kc*64);
    #pragma unroll
    for (int j = 0; j < 16; ++j){
      ulonglong2 u = Wg[j];
      wv[2*j] = u.x; wv[2*j+1] = u.y;
    }
  }

  // ---- one-time smem staging ----
  for (int i = tid; i < INDIM*128; i += NTHR){
    int c0 = i >> 7, r = i & 127;
    int uu = r >> 2, g = r & 3;
    WihT[c0*128 + r] = Wih[(g*HID + uc*32 + uu)*INDIM + c0];
  }
  for (int i = tid; i < 128; i += NTHR){
    int uu = i >> 2, g = i & 3;
    int grr = g*HID + uc*32 + uu;
    biasS[i] = bih[grr] + bhh[grr];
  }
  for (int i = tid; i < BPC*HID; i += NTHR){
    int b = i >> 8, k = i & 255;
    hbuf[b*HROW + (k >> 6)*68 + (k & 63)] = H0[(gb0 + b)*(2*HID) + k];
  }

  if (tid == 0){
    mbar_init(sb + OFF_MBAR,     1);
    mbar_init(sb + OFF_MBAR + 8, 1);
    mbar_arm (sb + OFF_MBAR,     EXCH_BYTES);
    mbar_arm (sb + OFF_MBAR + 8, EXCH_BYTES);
  }
  __syncthreads();
  asm volatile("barrier.cluster.arrive.aligned;" ::: "memory");
  asm volatile("barrier.cluster.wait.aligned;"   ::: "memory");

  // per-lane constants from smem (after staging)
  const float w80 = WihT[80*128 + ro];
  const float w81 = WihT[81*128 + ro];
  const float bs  = biasS[ro];

  // cell state for this unit, all 8 batches (redundant across the 16 lanes of a unit)
  float cst[8], hl[8];
  #pragma unroll
  for (int b = 0; b < 8; ++b){
    cst[b] = H0[(gb0 + b)*(2*HID) + HID + ug];
    hl[b] = 0.f;
  }

  // remote CTA smem bases
  uint32_t ra[CLU];
  #pragma unroll
  for (int p = 0; p < CLU; ++p) ra[p] = mapa_u32(sb, p);

  // exchange: lanes j = gq*4+kc < 8 send to CTA p=j (covers both u' groups)
  const int j16 = gq*4 + kc;
  const bool sender = (j16 < 8);
  const bool writer = (j16 == 0);
  const uint32_t raj = sender ? ra[j16] : 0;
  const unsigned hoff_u = 4u*(unsigned)((ug >> 6)*68 + (ug & 63));  // within b-row

  // input fetch identity: lane sel/bb
  const int sel = lane >> 3, bb = lane & 7;
  const unsigned* ipb;
  {
    const unsigned* p = (sel == 0) ? (const unsigned*)X :
                        (sel == 1) ? (const unsigned*)A :
                        (sel == 2) ? (const unsigned*)R : (const unsigned*)Dn;
    ipb = p + (size_t)(gb0 + bb)*TSTEPS;
  }

  uint32_t ph0 = 0, ph1 = 0;

  #pragma unroll 1
  for (int t = 0; t < TSTEPS; ++t){
    const int cb = t & 1;
    const int nb = cb ^ 1;

    // issue input load before the wait (independent of h)
    unsigned inw = ipb[t];

    if (t > 0){
      uint32_t m = sb + OFF_MBAR + cb*8;
      uint32_t par = cb ? ph1 : ph0;
      mbar_wait(m, par);
      if (cb) ph1 ^= 1; else ph0 ^= 1;
      if (tid == 0) mbar_arm(m, EXCH_BYTES);
    }

    const float* hB = hbuf + cb*HBUFLEN;
    const unsigned nboff = (unsigned)(OFF_HBUF) + (unsigned)(nb*HBUFLEN*4);
    const unsigned moff  = (unsigned)(OFF_MBAR + nb*8);

    #pragma unroll
    for (int b = 0; b < 8; ++b){
      // ---- GEMM partial: this lane's gate row x h[b][kc*64..+64) ----
      const ulonglong2* hp = (const ulonglong2*)(hB + b*HROW + kc*68);
      ull a0 = 0, a1 = 0;
      #pragma unroll
      for (int j = 0; j < 8; ++j){
        ulonglong2 u = hp[j];
        a0 = fma2(wv[2*j],     u.x, a0);
        a0 = fma2(wv[2*j+1],   u.y, a0);
      }
      #pragma unroll
      for (int j = 8; j < 16; ++j){
        ulonglong2 u = hp[j];
        a1 = fma2(wv[2*j],     u.x, a1);
        a1 = fma2(wv[2*j+1],   u.y, a1);
      }
      ull asum = fma2(a0, 0x3f8000003f800000ull /*1.0,1.0*/, a1); // a0+a1 packed
      float s = lo32(asum) + hi32(asum);

      // reduce over kc (lane bits 0-1)
      s += __shfl_xor_sync(0xffffffffu, s, 1);
      s += __shfl_xor_sync(0xffffffffu, s, 2);

      // x_proj for this lane's gate
      int   xi = __shfl_sync(0xffffffffu, (int)inw, b);
      int   ai = __shfl_sync(0xffffffffu, (int)inw, 8 + b);
      float rv = __uint_as_float(__shfl_sync(0xffffffffu, inw, 16 + b));
      float dv = __uint_as_float(__shfl_sync(0xffffffffu, inw, 24 + b));
      float gate = s + WihT[xi*128 + ro] + WihT[(64 + ai)*128 + ro]
                 + w80*rv + w81*dv + bs;

      // activation of own gate (tanh for g-gate, sigmoid otherwise)
      float act = (gq == 2) ? tanhf_(gate) : sigf(gate);

      // gather i,f,g,o across gate lanes (bits 2-3)
      float axa = __shfl_xor_sync(0xffffffffu, act, 4);
      float e0 = (gq & 1) ? axa : act;   // act(gq & ~1)
      float e1 = (gq & 1) ? act : axa;   // act(gq | 1)
      float f0 = __shfl_xor_sync(0xffffffffu, e0, 8);
      float f1 = __shfl_xor_sync(0xffffffffu, e1, 8);
      float vI = (gq < 2) ? e0 : f0;
      float vF = (gq < 2) ? e1 : f1;
      float vG = (gq < 2) ? f0 : e0;
      float vO = (gq < 2) ? f1 : e1;

      float cc = vF*cst[b] + vI*vG;
      cst[b] = cc;
      float hv = vO * tanhf_(cc);
      hl[b] = hv;

      // features[b][t][u]
      if (writer)
        out[((size_t)(gb0 + b)*TSTEPS + t)*HID + ug] = hv;

      // send h for step t+1 to all CTAs (8 sender lanes x 2 units)
      if (t < TSTEPS-1 && sender){
        unsigned ho = nboff + (unsigned)(b*HROW*4) + hoff_u;
        st_async_f32(raj + ho, hv, raj + moff);
      }
    }
  }

  // final_hidden = [hT | cT]
  if (writer){
    size_t fo = (size_t)BATCH*TSTEPS*HID;
    #pragma unroll
    for (int b = 0; b < 8; ++b){
      out[fo + (size_t)(gb0 + b)*(2*HID) + ug]       = hl[b];
      out[fo + (size_t)(gb0 + b)*(2*HID) + HID + ug] = cst[b];
    }
  }

  asm volatile("barrier.cluster.arrive.aligned;" ::: "memory");
  asm volatile("barrier.cluster.wait.aligned;"   ::: "memory");
}

extern "C" void kernel_launch(void* const* d_in, const int* in_sizes, int n_in,
                              void* d_out, int out_size)
{
  const int*   X   = (const int*)  d_in[0];
  const float* H0  = (const float*)d_in[1];
  const int*   A   = (const int*)  d_in[2];
  const float* R   = (const float*)d_in[3];
  const float* Dn  = (const float*)d_in[4];
  const float* Wih = (const float*)d_in[5];
  const float* Whh = (const float*)d_in[6];
  const float* bih = (const float*)d_in[7];
  const float* bhh = (const float*)d_in[8];
  float* out = (float*)d_out;

  cudaFuncSetAttribute(lstm_scan_kernel,
                       cudaFuncAttributeMaxDynamicSharedMemorySize, SMEM_TOTAL);
  lstm_scan_kernel<<<BATCH, NTHR, SMEM_TOTAL>>>(X, H0, A, R, Dn, Wih, Whh, bih, bhh, out);
}

// round 10
// speedup vs baseline: 1.0009x; 1.0005x over previous
#include <cuda_runtime.h>
#include <cstdint>

#define TSTEPS 2048
#define BATCH  128
#define HID    256
#define INDIM  82
#define CLU    8
#define BPC    8
#define NTHR   512

#define HROW    272              // padded floats per batch row: 4 chunks of 68
#define HBUFLEN (BPC*HROW)       // 2176 floats per phase

// ---- shared memory layout (bytes) ----
#define OFF_WIH   0                       // [col][ro] ro = ul*4+g (unit-major)
#define SZ_WIH    (INDIM*128*4)           // 41984
#define OFF_BIAS  (OFF_WIH + SZ_WIH)      // 41984
#define SZ_BIAS   (512)
#define OFF_HBUF  (OFF_BIAS + SZ_BIAS)    // 42496 (16B aligned)
#define SZ_HBUF   (2*HBUFLEN*4)           // 17408
#define OFF_MBAR  (OFF_HBUF + SZ_HBUF)    // 59904
#define SMEM_TOTAL (OFF_MBAR + 16)

#define EXCH_BYTES (CLU*BPC*32*4)         // 8192 B arriving per phase per CTA

typedef unsigned long long ull;

__device__ __forceinline__ ull fma2(ull a, ull b, ull c){
  ull d; asm("fma.rn.f32x2 %0, %1, %2, %3;" : "=l"(d) : "l"(a),"l"(b),"l"(c)); return d;
}
__device__ __forceinline__ float lo32(ull v){ return __uint_as_float((unsigned)(v & 0xffffffffull)); }
__device__ __forceinline__ float hi32(ull v){ return __uint_as_float((unsigned)(v >> 32)); }
__device__ __forceinline__ float sigf(float x){ return __fdividef(1.f, 1.f + __expf(-x)); }
__device__ __forceinline__ float tanhf_(float x){ return __fdividef(2.f, 1.f + __expf(-2.f*x)) - 1.f; }
__device__ __forceinline__ uint32_t s2u(const void* p){
  uint32_t a;
  asm("{.reg .u64 t; cvta.to.shared.u64 t, %1; cvt.u32.u64 %0, t;}" : "=r"(a) : "l"(p));
  return a;
}
__device__ __forceinline__ void mbar_init(uint32_t m, int cnt){
  asm volatile("mbarrier.init.shared.b64 [%0], %1;" :: "r"(m), "r"(cnt) : "memory");
}
__device__ __forceinline__ void mbar_arm(uint32_t m, int bytes){
  asm volatile("mbarrier.arrive.expect_tx.shared.b64 _, [%0], %1;" :: "r"(m), "r"(bytes) : "memory");
}
__device__ __forceinline__ void mbar_wait(uint32_t m, uint32_t parity){
  asm volatile(
    "{\n\t.reg .pred P;\n\t"
    "WLP%=:\n\t"
    "mbarrier.try_wait.parity.acquire.cluster.shared::cta.b64 P, [%0], %1, 0x989680;\n\t"
    "@!P bra WLP%=;\n\t}"
    :: "r"(m), "r"(parity) : "memory");
}
__device__ __forceinline__ void st_async_f32(uint32_t raddr, float v, uint32_t rmbar){
  asm volatile("st.async.shared::cluster.mbarrier::complete_tx::bytes.b32 [%0], %1, [%2];"
               :: "r"(raddr), "r"(__float_as_uint(v)), "r"(rmbar) : "memory");
}
__device__ __forceinline__ uint32_t mapa_u32(uint32_t la, int rank){
  uint32_t ra;
  asm("mapa.shared::cluster.u32 %0, %1, %2;" : "=r"(ra) : "r"(la), "r"(rank));
  return ra;
}

extern __shared__ char smem[];

__global__ void __cluster_dims__(CLU,1,1) __launch_bounds__(NTHR,1)
lstm_scan_kernel(const int* __restrict__ X, const float* __restrict__ H0,
                 const int* __restrict__ A, const float* __restrict__ R,
                 const float* __restrict__ Dn,
                 const float* __restrict__ Wih, const float* __restrict__ Whh,
                 const float* __restrict__ bih, const float* __restrict__ bhh,
                 float* __restrict__ out)
{
  const int tid = threadIdx.x;
  const int uc  = blockIdx.x & (CLU-1);   // cluster rank: which 32 hidden units
  const int bg  = blockIdx.x / CLU;       // batch group of 8
  const int gb0 = bg * BPC;

  float* WihT  = (float*)(smem + OFF_WIH);
  float* biasS = (float*)(smem + OFF_BIAS);
  float* hbuf  = (float*)(smem + OFF_HBUF);

  const uint32_t sb = s2u(smem);

  // ---- lane identity: lane = u'(b4) | gq(b3:2) | kc(b1:0) ----
  const int w    = tid >> 5;
  const int lane = tid & 31;
  const int up   = lane >> 4;          // which of the warp's 2 units
  const int gq   = (lane >> 2) & 3;    // gate (i,f,g,o)
  const int kc   = lane & 3;           // k-chunk of 64
  const int ul   = w*2 + up;           // local unit 0..31
  const int ug   = uc*32 + ul;         // global unit 0..255
  const int ro   = ul*4 + gq;          // unit-major row index for WihT/bias
  const int gr   = gq*HID + ug;        // global gate-row in W

  // ---- weight-stationary: this lane's 64 W_hh floats in registers ----
  ull wv[32];
  {
    const ulonglong2* Wg = (const ulonglong2*)(Whh + (size_t)gr*HID + kc*64);
    #pragma unroll
    for (int j = 0; j < 16; ++j){
      ulonglong2 u = Wg[j];
      wv[2*j] = u.x; wv[2*j+1] = u.y;
    }
  }

  // ---- one-time smem staging ----
  for (int i = tid; i < INDIM*128; i += NTHR){
    int c0 = i >> 7, r = i & 127;
    int uu = r >> 2, g = r & 3;
    WihT[c0*128 + r] = Wih[(g*HID + uc*32 + uu)*INDIM + c0];
  }
  for (int i = tid; i < 128; i += NTHR){
    int uu = i >> 2, g = i & 3;
    int grr = g*HID + uc*32 + uu;
    biasS[i] = bih[grr] + bhh[grr];
  }
  for (int i = tid; i < BPC*HID; i += NTHR){
    int b = i >> 8, k = i & 255;
    hbuf[b*HROW + (k >> 6)*68 + (k & 63)] = H0[(gb0 + b)*(2*HID) + k];
  }

  if (tid == 0){
    mbar_init(sb + OFF_MBAR,     1);
    mbar_init(sb + OFF_MBAR + 8, 1);
    mbar_arm (sb + OFF_MBAR,     EXCH_BYTES);
    mbar_arm (sb + OFF_MBAR + 8, EXCH_BYTES);
  }
  __syncthreads();
  asm volatile("barrier.cluster.arrive.aligned;" ::: "memory");
  asm volatile("barrier.cluster.wait.aligned;"   ::: "memory");

  // per-lane constants from smem (after staging)
  const float w80 = WihT[80*128 + ro];
  const float w81 = WihT[81*128 + ro];
  const float bs  = biasS[ro];

  // cell state for this unit, all 8 batches (redundant across the 16 lanes of a unit)
  float cst[8], hl[8];
  #pragma unroll
  for (int b = 0; b < 8; ++b){
    cst[b] = H0[(gb0 + b)*(2*HID) + HID + ug];
    hl[b] = 0.f;
  }

  // remote CTA smem bases
  uint32_t ra[CLU];
  #pragma unroll
  for (int p = 0; p < CLU; ++p) ra[p] = mapa_u32(sb, p);

  // exchange: lanes j = gq*4+kc < 8 send to CTA p=j (covers both u' groups)
  const int j16 = gq*4 + kc;
  const bool sender = (j16 < 8);
  const bool writer = (j16 == 0);
  const uint32_t raj = sender ? ra[j16] : 0;
  const unsigned hoff_u = 4u*(unsigned)((ug >> 6)*68 + (ug & 63));  // within b-row

  // input fetch identity: lane sel/bb
  const int sel = lane >> 3, bb = lane & 7;
  const unsigned* ipb;
  {
    const unsigned* p = (sel == 0) ? (const unsigned*)X :
                        (sel == 1) ? (const unsigned*)A :
                        (sel == 2) ? (const unsigned*)R : (const unsigned*)Dn;
    ipb = p + (size_t)(gb0 + bb)*TSTEPS;
  }

  uint32_t ph0 = 0, ph1 = 0;

  #pragma unroll 1
  for (int t = 0; t < TSTEPS; ++t){
    const int cb = t & 1;
    const int nb = cb ^ 1;

    // issue input load before the wait (independent of h)
    unsigned inw = ipb[t];

    if (t > 0){
      uint32_t m = sb + OFF_MBAR + cb*8;
      uint32_t par = cb ? ph1 : ph0;
      mbar_wait(m, par);
      if (cb) ph1 ^= 1; else ph0 ^= 1;
      if (tid == 0) mbar_arm(m, EXCH_BYTES);
    }

    const float* hB = hbuf + cb*HBUFLEN;
    const unsigned nboff = (unsigned)(OFF_HBUF) + (unsigned)(nb*HBUFLEN*4);
    const unsigned moff  = (unsigned)(OFF_MBAR + nb*8);

    #pragma unroll
    for (int b = 0; b < 8; ++b){
      // ---- GEMM partial: this lane's gate row x h[b][kc*64..+64) ----
      const ulonglong2* hp = (const ulonglong2*)(hB + b*HROW + kc*68);
      ull a0 = 0, a1 = 0;
      #pragma unroll
      for (int j = 0; j < 8; ++j){
        ulonglong2 u = hp[j];
        a0 = fma2(wv[2*j],     u.x, a0);
        a0 = fma2(wv[2*j+1],   u.y, a0);
      }
      #pragma unroll
      for (int j = 8; j < 16; ++j){
        ulonglong2 u = hp[j];
        a1 = fma2(wv[2*j],     u.x, a1);
        a1 = fma2(wv[2*j+1],   u.y, a1);
      }
      ull asum = fma2(a0, 0x3f8000003f800000ull /*1.0,1.0*/, a1); // a0+a1 packed
      float s = lo32(asum) + hi32(asum);

      // reduce over kc (lane bits 0-1)
      s += __shfl_xor_sync(0xffffffffu, s, 1);
      s += __shfl_xor_sync(0xffffffffu, s, 2);

      // x_proj for this lane's gate
      int   xi = __shfl_sync(0xffffffffu, (int)inw, b);
      int   ai = __shfl_sync(0xffffffffu, (int)inw, 8 + b);
      float rv = __uint_as_float(__shfl_sync(0xffffffffu, inw, 16 + b));
      float dv = __uint_as_float(__shfl_sync(0xffffffffu, inw, 24 + b));
      float gate = s + WihT[xi*128 + ro] + WihT[(64 + ai)*128 + ro]
                 + w80*rv + w81*dv + bs;

      // activation of own gate (tanh for g-gate, sigmoid otherwise)
      float act = (gq == 2) ? tanhf_(gate) : sigf(gate);

      // gather i,f,g,o across gate lanes (bits 2-3)
      float axa = __shfl_xor_sync(0xffffffffu, act, 4);
      float e0 = (gq & 1) ? axa : act;   // act(gq & ~1)
      float e1 = (gq & 1) ? act : axa;   // act(gq | 1)
      float f0 = __shfl_xor_sync(0xffffffffu, e0, 8);
      float f1 = __shfl_xor_sync(0xffffffffu, e1, 8);
      float vI = (gq < 2) ? e0 : f0;
      float vF = (gq < 2) ? e1 : f1;
      float vG = (gq < 2) ? f0 : e0;
      float vO = (gq < 2) ? f1 : e1;

      float cc = vF*cst[b] + vI*vG;
      cst[b] = cc;
      float hv = vO * tanhf_(cc);
      hl[b] = hv;

      // features[b][t][u]
      if (writer)
        out[((size_t)(gb0 + b)*TSTEPS + t)*HID + ug] = hv;

      // send h for step t+1 to all CTAs (8 sender lanes x 2 units)
      if (t < TSTEPS-1 && sender){
        unsigned ho = nboff + (unsigned)(b*HROW*4) + hoff_u;
        st_async_f32(raj + ho, hv, raj + moff);
      }
    }
  }

  // final_hidden = [hT | cT]
  if (writer){
    size_t fo = (size_t)BATCH*TSTEPS*HID;
    #pragma unroll
    for (int b = 0; b < 8; ++b){
      out[fo + (size_t)(gb0 + b)*(2*HID) + ug]       = hl[b];
      out[fo + (size_t)(gb0 + b)*(2*HID) + HID + ug] = cst[b];
    }
  }

  asm volatile("barrier.cluster.arrive.aligned;" ::: "memory");
  asm volatile("barrier.cluster.wait.aligned;"   ::: "memory");
}

extern "C" void kernel_launch(void* const* d_in, const int* in_sizes, int n_in,
                              void* d_out, int out_size)
{
  const int*   X   = (const int*)  d_in[0];
  const float* H0  = (const float*)d_in[1];
  const int*   A   = (const int*)  d_in[2];
  const float* R   = (const float*)d_in[3];
  const float* Dn  = (const float*)d_in[4];
  const float* Wih = (const float*)d_in[5];
  const float* Whh = (const float*)d_in[6];
  const float* bih = (const float*)d_in[7];
  const float* bhh = (const float*)d_in[8];
  float* out = (float*)d_out;

  cudaFuncSetAttribute(lstm_scan_kernel,
                       cudaFuncAttributeMaxDynamicSharedMemorySize, SMEM_TOTAL);
  lstm_scan_kernel<<<BATCH, NTHR, SMEM_TOTAL>>>(X, H0, A, R, Dn, Wih, Whh, bih, bhh, out);
}